// round 4
// baseline (speedup 1.0000x reference)
#include <cuda_runtime.h>
#include <math.h>

#define B_ 64
#define L_ 512
#define E_ 64
#define H_ 8
#define D_ 8
#define ROWS (B_*L_)          // 32768
#define QK_SCALE 0.35355339059327373f   // 1/sqrt(8)
#define LOG2E_F  1.4426950408889634f
#define SLICE 256             // keys per slice-warp (L/2)

typedef unsigned long long u64t;

// ---- packed f32x2 helpers (ptxas never auto-fuses; PTX only) ----
__device__ __forceinline__ u64t fma2(u64t a, u64t b, u64t c) {
    u64t d; asm("fma.rn.f32x2 %0, %1, %2, %3;" : "=l"(d) : "l"(a), "l"(b), "l"(c)); return d;
}
__device__ __forceinline__ u64t mul2(u64t a, u64t b) {
    u64t d; asm("mul.rn.f32x2 %0, %1, %2;" : "=l"(d) : "l"(a), "l"(b)); return d;
}
__device__ __forceinline__ u64t add2(u64t a, u64t b) {
    u64t d; asm("add.rn.f32x2 %0, %1, %2;" : "=l"(d) : "l"(a), "l"(b)); return d;
}
__device__ __forceinline__ u64t pack2(float lo, float hi) {
    u64t d; asm("mov.b64 %0, {%1, %2};" : "=l"(d) : "f"(lo), "f"(hi)); return d;
}
__device__ __forceinline__ void unpack2(u64t a, float& lo, float& hi) {
    asm("mov.b64 {%0, %1}, %2;" : "=f"(lo), "=f"(hi) : "l"(a));
}
__device__ __forceinline__ float ex2f(float x) {
    float r; asm("ex2.approx.f32 %0, %1;" : "=f"(r) : "f"(x)); return r;
}

// ---- scratch (static device arrays; no allocation) ----
__device__ float g_qh [ROWS*E_];
__device__ float g_kh [ROWS*E_];
__device__ float g_vh [ROWS*E_];
__device__ float g_ctx[ROWS*E_];
__device__ float g_t0 [ROWS*E_];
__device__ float g_x  [ROWS*E_];
__device__ float g_f1 [ROWS*E_];
__device__ float g_inv[ROWS*H_];

// ---------------------------------------------------------------------------
// Generic 64-wide GEMM: Y[r][e] = act( scale * ( sum_j X[r][j]*W[e][j] + bias[e] ) )
// dh_transpose: remap OUTPUT column (h*8+d) -> (d*8+h)   (produce attn layout)
// wperm:        remap W's j index (input cols of X are in d*8+h layout)
// ---------------------------------------------------------------------------
__global__ __launch_bounds__(256) void gemm64(
    const float* __restrict__ X, const float* __restrict__ W,
    const float* __restrict__ bias, float* __restrict__ Y,
    float scale, int relu, int dh_transpose, int wperm)
{
    __shared__ float Wt[64][65];
    __shared__ float xs[64][64];

    const int t = threadIdx.x;
    const int rowbase = blockIdx.x * 64;

#pragma unroll
    for (int kk = 0; kk < 16; kk++) {
        int idx = t + kk * 256;
        int r = idx >> 6, c = idx & 63;
        xs[r][c] = X[(size_t)(rowbase + r) * 64 + c];
        int cc = wperm ? ((c & 7) * 8 + (c >> 3)) : c;
        Wt[cc][r] = W[idx];
    }
    __syncthreads();

    const int tx = t & 15;
    const int ty = t >> 4;

    float acc[4][4];
#pragma unroll
    for (int a = 0; a < 4; a++)
#pragma unroll
        for (int c = 0; c < 4; c++) acc[a][c] = 0.0f;

#pragma unroll 4
    for (int j = 0; j < 64; j++) {
        float xv[4], wv[4];
#pragma unroll
        for (int rr = 0; rr < 4; rr++) xv[rr] = xs[ty * 4 + rr][j];
#pragma unroll
        for (int c = 0; c < 4; c++)   wv[c] = Wt[j][tx + c * 16];
#pragma unroll
        for (int rr = 0; rr < 4; rr++)
#pragma unroll
            for (int c = 0; c < 4; c++)
                acc[rr][c] = fmaf(xv[rr], wv[c], acc[rr][c]);
    }

#pragma unroll
    for (int c = 0; c < 4; c++) {
        int col = tx + c * 16;
        float bb = bias[col];
        int ocol = dh_transpose ? ((col & 7) * 8 + (col >> 3)) : col;
#pragma unroll
        for (int rr = 0; rr < 4; rr++) {
            float v = scale * (acc[rr][c] + bb);
            if (relu) v = fmaxf(v, 0.0f);
            Y[(size_t)(rowbase + ty * 4 + rr) * 64 + ocol] = v;
        }
    }
}

// ---------------------------------------------------------------------------
// Attention pass 1: softmax denominators, split-K over 2 slices.
// Block 128 thr = 4 warps: warp = qg*2 + s  (qg in {0,1}: 32 queries each;
// s in {0,1}: key slice [s*256, s*256+256)). Lane owns one query, all 8 heads.
// q/k in [d*8+h] layout; q pre-scaled by QK_SCALE*log2(e); e = ex2(q.k).
// ---------------------------------------------------------------------------
__global__ __launch_bounds__(128, 5) void attn_pass1(
    const float* __restrict__ qh, const float* __restrict__ kh,
    float* __restrict__ invout)
{
    __shared__ float part[4][32][8];

    const int b    = blockIdx.y;
    const int tid  = threadIdx.x;
    const int warp = tid >> 5;
    const int lane = tid & 31;
    const int qg   = warp >> 1;
    const int s    = warp & 1;
    const size_t qi = (size_t)b * L_ + blockIdx.x * 64 + qg * 32 + lane;

    u64t q2[32];
    {
        const ulonglong2* qp = (const ulonglong2*)(qh + qi * 64);
#pragma unroll
        for (int j = 0; j < 16; j++) {
            ulonglong2 v = qp[j];
            q2[2 * j] = v.x; q2[2 * j + 1] = v.y;
        }
    }

    float sum[8];
#pragma unroll
    for (int h = 0; h < 8; h++) sum[h] = 0.0f;

    const float* kb = kh + ((size_t)b * L_ + s * SLICE) * 64;
#pragma unroll 2
    for (int m = 0; m < SLICE; m++) {
        const ulonglong2* kp = (const ulonglong2*)(kb + (size_t)m * 64);
        u64t acc[4];
        {
            ulonglong2 ka = kp[0], kc = kp[1];
            acc[0] = mul2(q2[0], ka.x);
            acc[1] = mul2(q2[1], ka.y);
            acc[2] = mul2(q2[2], kc.x);
            acc[3] = mul2(q2[3], kc.y);
        }
#pragma unroll
        for (int d = 1; d < 8; d++) {
            ulonglong2 ka = kp[2 * d], kc = kp[2 * d + 1];
            acc[0] = fma2(q2[d * 4 + 0], ka.x, acc[0]);
            acc[1] = fma2(q2[d * 4 + 1], ka.y, acc[1]);
            acc[2] = fma2(q2[d * 4 + 2], kc.x, acc[2]);
            acc[3] = fma2(q2[d * 4 + 3], kc.y, acc[3]);
        }
#pragma unroll
        for (int p = 0; p < 4; p++) {
            float lo, hi; unpack2(acc[p], lo, hi);
            sum[2 * p]     += ex2f(lo);
            sum[2 * p + 1] += ex2f(hi);
        }
    }

    ((float4*)part[warp][lane])[0] = make_float4(sum[0], sum[1], sum[2], sum[3]);
    ((float4*)part[warp][lane])[1] = make_float4(sum[4], sum[5], sum[6], sum[7]);
    __syncthreads();

    if (s == 0) {
        float4 a0 = ((float4*)part[warp][lane])[0];
        float4 a1 = ((float4*)part[warp][lane])[1];
        float4 b0 = ((float4*)part[warp + 1][lane])[0];
        float4 b1 = ((float4*)part[warp + 1][lane])[1];
        float4* op = (float4*)(invout + qi * 8);
        op[0] = make_float4(1.0f / (a0.x + b0.x), 1.0f / (a0.y + b0.y),
                            1.0f / (a0.z + b0.z), 1.0f / (a0.w + b0.w));
        op[1] = make_float4(1.0f / (a1.x + b1.x), 1.0f / (a1.y + b1.y),
                            1.0f / (a1.z + b1.z), 1.0f / (a1.w + b1.w));
    }
}

// ---------------------------------------------------------------------------
// Attention pass 2: ctx (split-K partials reduced via smem) + attn_wts.
// Same warp mapping as pass 1. attn_wts staged per warp in 32x33 tiles.
// ctx kept unnormalized per slice; summed then scaled by inv at the end.
// ---------------------------------------------------------------------------
__global__ __launch_bounds__(128, 3) void attn_pass2(
    const float* __restrict__ qh, const float* __restrict__ kh,
    const float* __restrict__ vh, const float* __restrict__ invin,
    float* __restrict__ ctx_out, float* __restrict__ attn_out)
{
    __shared__ float Wtile[4][32][33];   // 16896B; reused as ctx stage [2][32][66]

    const int b    = blockIdx.y;
    const int tid  = threadIdx.x;
    const int warp = tid >> 5;
    const int lane = tid & 31;
    const int qg   = warp >> 1;
    const int s    = warp & 1;
    const size_t qi = (size_t)b * L_ + blockIdx.x * 64 + qg * 32 + lane;

    u64t q2[32];
    {
        const ulonglong2* qp = (const ulonglong2*)(qh + qi * 64);
#pragma unroll
        for (int j = 0; j < 16; j++) {
            ulonglong2 v = qp[j];
            q2[2 * j] = v.x; q2[2 * j + 1] = v.y;
        }
    }
    float inv[8];
    {
        const float4* ip = (const float4*)(invin + qi * 8);
        float4 a = ip[0], c = ip[1];
        inv[0] = a.x; inv[1] = a.y; inv[2] = a.z; inv[3] = a.w;
        inv[4] = c.x; inv[5] = c.y; inv[6] = c.z; inv[7] = c.w;
    }

    u64t ctx2[32];
#pragma unroll
    for (int j = 0; j < 32; j++) ctx2[j] = 0ull;

    const float* kb = kh + ((size_t)b * L_ + s * SLICE) * 64;
    const float* vb = vh + ((size_t)b * L_ + s * SLICE) * 64;

    for (int m0 = 0; m0 < SLICE; m0 += 32) {
#pragma unroll 2
        for (int mm = 0; mm < 32; mm++) {
            const int m = m0 + mm;
            const ulonglong2* kp = (const ulonglong2*)(kb + (size_t)m * 64);
            u64t acc[4];
            {
                ulonglong2 ka = kp[0], kc = kp[1];
                acc[0] = mul2(q2[0], ka.x);
                acc[1] = mul2(q2[1], ka.y);
                acc[2] = mul2(q2[2], kc.x);
                acc[3] = mul2(q2[3], kc.y);
            }
#pragma unroll
            for (int d = 1; d < 8; d++) {
                ulonglong2 ka = kp[2 * d], kc = kp[2 * d + 1];
                acc[0] = fma2(q2[d * 4 + 0], ka.x, acc[0]);
                acc[1] = fma2(q2[d * 4 + 1], ka.y, acc[1]);
                acc[2] = fma2(q2[d * 4 + 2], kc.x, acc[2]);
                acc[3] = fma2(q2[d * 4 + 3], kc.y, acc[3]);
            }
            float e[8];
#pragma unroll
            for (int p = 0; p < 4; p++) {
                float lo, hi; unpack2(acc[p], lo, hi);
                e[2 * p]     = ex2f(lo);
                e[2 * p + 1] = ex2f(hi);
            }
            // head-mean of normalized softmax
            float w = e[0] * inv[0];
#pragma unroll
            for (int h = 1; h < 8; h++) w = fmaf(e[h], inv[h], w);
            Wtile[warp][lane][mm] = w * 0.125f;

            u64t e2[4];
#pragma unroll
            for (int p = 0; p < 4; p++) e2[p] = pack2(e[2 * p], e[2 * p + 1]);

            const ulonglong2* vp = (const ulonglong2*)(vb + (size_t)m * 64);
#pragma unroll
            for (int d = 0; d < 8; d++) {
                ulonglong2 va = vp[2 * d], vc = vp[2 * d + 1];
                ctx2[d * 4 + 0] = fma2(e2[0], va.x, ctx2[d * 4 + 0]);
                ctx2[d * 4 + 1] = fma2(e2[1], va.y, ctx2[d * 4 + 1]);
                ctx2[d * 4 + 2] = fma2(e2[2], vc.x, ctx2[d * 4 + 2]);
                ctx2[d * 4 + 3] = fma2(e2[3], vc.y, ctx2[d * 4 + 3]);
            }
        }
        // flush 32 queries x 32 keys (transposed -> coalesced rows)
        __syncwarp();
        float* arow = attn_out +
            ((size_t)b * L_ + blockIdx.x * 64 + qg * 32) * L_ + s * SLICE + m0;
#pragma unroll
        for (int r = 0; r < 32; r++)
            arow[(size_t)r * L_ + lane] = Wtile[warp][r][lane];
        __syncwarp();
    }

    // ---- combine ctx partials across the two slices ----
    __syncthreads();
    float* cstage = (float*)Wtile;                 // [2][32][66] = 4224 floats
    const int base = (qg * 32 + lane) * 66;
    if (s == 1) {
#pragma unroll
        for (int j = 0; j < 32; j++) {
            int d = j >> 2, p = j & 3;
            *(u64t*)(cstage + base + d * 8 + 2 * p) = ctx2[j];
        }
    }
    __syncthreads();
    if (s == 0) {
        u64t inv2[4];
#pragma unroll
        for (int p = 0; p < 4; p++) inv2[p] = pack2(inv[2 * p], inv[2 * p + 1]);
#pragma unroll
        for (int j = 0; j < 32; j++) {
            int d = j >> 2, p = j & 3;
            u64t other = *(u64t*)(cstage + base + d * 8 + 2 * p);
            ctx2[j] = mul2(add2(ctx2[j], other), inv2[p]);
        }
        // store ctx row in [d*8+h] layout (Wo gemm uses wperm)
        ulonglong2* cp = (ulonglong2*)(ctx_out + qi * 64);
#pragma unroll
        for (int d = 0; d < 8; d++) {
            ulonglong2 a, c;
            a.x = ctx2[d * 4 + 0]; a.y = ctx2[d * 4 + 1];
            c.x = ctx2[d * 4 + 2]; c.y = ctx2[d * 4 + 3];
            cp[2 * d] = a; cp[2 * d + 1] = c;
        }
    }
}

// ---------------------------------------------------------------------------
// Residual add + LayerNorm over E=64. One warp per row; lane covers 2 cols.
// ---------------------------------------------------------------------------
__global__ __launch_bounds__(256) void ln_add_kernel(
    const float* __restrict__ a, const float* __restrict__ bres,
    const float* __restrict__ g, const float* __restrict__ beta,
    float* __restrict__ out)
{
    const int warp = threadIdx.x >> 5;
    const int lane = threadIdx.x & 31;
    const int row  = blockIdx.x * 8 + warp;

    float2 av = ((const float2*)(a    + (size_t)row * 64))[lane];
    float2 bv = ((const float2*)(bres + (size_t)row * 64))[lane];
    float x0 = av.x + bv.x;
    float x1 = av.y + bv.y;

    float s  = x0 + x1;
    float sq = fmaf(x0, x0, x1 * x1);
#pragma unroll
    for (int o = 16; o > 0; o >>= 1) {
        s  += __shfl_xor_sync(0xffffffffu, s,  o);
        sq += __shfl_xor_sync(0xffffffffu, sq, o);
    }
    float mu   = s * (1.0f / 64.0f);
    float var  = sq * (1.0f / 64.0f) - mu * mu;
    float rstd = rsqrtf(var + 1e-5f);

    float2 gv = ((const float2*)g)[lane];
    float2 bb = ((const float2*)beta)[lane];
    float2 o2;
    o2.x = fmaf((x0 - mu) * rstd, gv.x, bb.x);
    o2.y = fmaf((x1 - mu) * rstd, gv.y, bb.y);
    ((float2*)(out + (size_t)row * 64))[lane] = o2;
}

// ---------------------------------------------------------------------------
extern "C" void kernel_launch(void* const* d_in, const int* in_sizes, int n_in,
                              void* d_out, int out_size)
{
    const float* q    = (const float*)d_in[0];
    const float* k    = (const float*)d_in[1];
    const float* prev = (const float*)d_in[2];
    const float* Wq   = (const float*)d_in[3];
    const float* bq   = (const float*)d_in[4];
    const float* Wk   = (const float*)d_in[5];
    const float* bk   = (const float*)d_in[6];
    const float* Wv   = (const float*)d_in[7];
    const float* bv   = (const float*)d_in[8];
    const float* Wo   = (const float*)d_in[9];
    const float* bo   = (const float*)d_in[10];
    const float* g1   = (const float*)d_in[11];
    const float* be1  = (const float*)d_in[12];
    const float* W1   = (const float*)d_in[13];
    const float* b1   = (const float*)d_in[14];
    const float* W2   = (const float*)d_in[15];
    const float* b2   = (const float*)d_in[16];
    const float* g2   = (const float*)d_in[17];
    const float* be2  = (const float*)d_in[18];

    float* outp = (float*)d_out;                    // [B, Lq, E]
    float* attn = outp + (size_t)ROWS * E_;         // [B, Lq, Lk]

    float *qh, *khp, *vhp, *ctx, *t0, *xbuf, *f1, *invb;
    cudaGetSymbolAddress((void**)&qh,  g_qh);
    cudaGetSymbolAddress((void**)&khp, g_kh);
    cudaGetSymbolAddress((void**)&vhp, g_vh);
    cudaGetSymbolAddress((void**)&ctx, g_ctx);
    cudaGetSymbolAddress((void**)&t0,  g_t0);
    cudaGetSymbolAddress((void**)&xbuf,g_x);
    cudaGetSymbolAddress((void**)&f1,  g_f1);
    cudaGetSymbolAddress((void**)&invb,g_inv);

    const int GB = ROWS / 64;   // 512 blocks per gemm
    // projections into [d*8+h] layout; q pre-scaled by QK_SCALE*log2(e)
    gemm64<<<GB, 256>>>(q, Wq, bq, qh,  QK_SCALE * LOG2E_F, 0, 1, 0);
    gemm64<<<GB, 256>>>(k, Wk, bk, khp, 1.0f, 0, 1, 0);
    gemm64<<<GB, 256>>>(k, Wv, bv, vhp, 1.0f, 0, 1, 0);

    attn_pass1<<<dim3(L_ / 64, B_), 128>>>(qh, khp, invb);
    attn_pass2<<<dim3(L_ / 64, B_), 128>>>(qh, khp, vhp, invb, ctx, attn);

    gemm64<<<GB, 256>>>(ctx, Wo, bo, t0, 1.0f, 0, 0, 1);
    ln_add_kernel<<<ROWS / 8, 256>>>(t0, prev, g1, be1, xbuf);

    gemm64<<<GB, 256>>>(xbuf, W1, b1, f1, 1.0f, 1, 0, 0);
    gemm64<<<GB, 256>>>(f1, W2, b2, t0, 1.0f, 0, 0, 0);
    ln_add_kernel<<<ROWS / 8, 256>>>(t0, xbuf, g2, be2, outp);
}

// round 5
// speedup vs baseline: 3.4414x; 3.4414x over previous
#include <cuda_runtime.h>
#include <math.h>

#define B_ 64
#define L_ 512
#define E_ 64
#define H_ 8
#define D_ 8
#define ROWS (B_*L_)          // 32768
#define QK_SCALE 0.35355339059327373f   // 1/sqrt(8)
#define LOG2E_F  1.4426950408889634f
#define NSL 4                 // key slices
#define SLK (L_/NSL)          // 128 keys per slice

typedef unsigned long long u64t;

// ---- packed f32x2 helpers (ptxas never auto-fuses; PTX only) ----
__device__ __forceinline__ u64t fma2(u64t a, u64t b, u64t c) {
    u64t d; asm("fma.rn.f32x2 %0, %1, %2, %3;" : "=l"(d) : "l"(a), "l"(b), "l"(c)); return d;
}
__device__ __forceinline__ u64t mul2(u64t a, u64t b) {
    u64t d; asm("mul.rn.f32x2 %0, %1, %2;" : "=l"(d) : "l"(a), "l"(b)); return d;
}
__device__ __forceinline__ u64t pack2(float lo, float hi) {
    u64t d; asm("mov.b64 %0, {%1, %2};" : "=l"(d) : "f"(lo), "f"(hi)); return d;
}
__device__ __forceinline__ void unpack2(u64t a, float& lo, float& hi) {
    asm("mov.b64 {%0, %1}, %2;" : "=f"(lo), "=f"(hi) : "l"(a));
}
__device__ __forceinline__ float ex2f(float x) {
    float r; asm("ex2.approx.f32 %0, %1;" : "=f"(r) : "f"(x)); return r;
}

// ---- scratch (static device arrays; no allocation) ----
__device__ float g_qh  [ROWS*E_];
__device__ float g_kh  [ROWS*E_];
__device__ float g_vh  [ROWS*E_];
__device__ float g_ctx [ROWS*E_];
__device__ float g_t0  [ROWS*E_];
__device__ float g_x   [ROWS*E_];
__device__ float g_f1  [ROWS*E_];
__device__ float g_inv [ROWS*H_];
__device__ float g_p1  [ROWS*NSL*H_];     // per-slice denominator partials (4MB)
__device__ float g_ctxp[NSL*ROWS*E_];     // per-slice ctx partials (32MB)

// ---------------------------------------------------------------------------
// Generic 64-wide GEMM: Y[r][e] = act( scale * ( sum_j X[r][j]*W[e][j] + bias[e] ) )
// dh_transpose: remap OUTPUT column (h*8+d) -> (d*8+h)   (produce attn layout)
// wperm:        remap W's j index (input cols of X are in d*8+h layout)
// ---------------------------------------------------------------------------
__global__ __launch_bounds__(256) void gemm64(
    const float* __restrict__ X, const float* __restrict__ W,
    const float* __restrict__ bias, float* __restrict__ Y,
    float scale, int relu, int dh_transpose, int wperm)
{
    __shared__ float Wt[64][65];
    __shared__ float xs[64][64];

    const int t = threadIdx.x;
    const int rowbase = blockIdx.x * 64;

#pragma unroll
    for (int kk = 0; kk < 16; kk++) {
        int idx = t + kk * 256;
        int r = idx >> 6, c = idx & 63;
        xs[r][c] = X[(size_t)(rowbase + r) * 64 + c];
        int cc = wperm ? ((c & 7) * 8 + (c >> 3)) : c;
        Wt[cc][r] = W[idx];
    }
    __syncthreads();

    const int tx = t & 15;
    const int ty = t >> 4;

    float acc[4][4];
#pragma unroll
    for (int a = 0; a < 4; a++)
#pragma unroll
        for (int c = 0; c < 4; c++) acc[a][c] = 0.0f;

#pragma unroll 4
    for (int j = 0; j < 64; j++) {
        float xv[4], wv[4];
#pragma unroll
        for (int rr = 0; rr < 4; rr++) xv[rr] = xs[ty * 4 + rr][j];
#pragma unroll
        for (int c = 0; c < 4; c++)   wv[c] = Wt[j][tx + c * 16];
#pragma unroll
        for (int rr = 0; rr < 4; rr++)
#pragma unroll
            for (int c = 0; c < 4; c++)
                acc[rr][c] = fmaf(xv[rr], wv[c], acc[rr][c]);
    }

#pragma unroll
    for (int c = 0; c < 4; c++) {
        int col = tx + c * 16;
        float bb = bias[col];
        int ocol = dh_transpose ? ((col & 7) * 8 + (col >> 3)) : col;
#pragma unroll
        for (int rr = 0; rr < 4; rr++) {
            float v = scale * (acc[rr][c] + bb);
            if (relu) v = fmaxf(v, 0.0f);
            Y[(size_t)(rowbase + ty * 4 + rr) * 64 + ocol] = v;
        }
    }
}

// ---------------------------------------------------------------------------
// Attention pass 1: per-slice softmax denominator partials.
// Grid (4 qtiles, 4 slices, B). Block 128 thr = 4 warps x 32 queries.
// Lane owns one query (all 8 heads); K staged in smem 64-key tiles; all
// lanes of a warp read the same K row -> broadcast LDS.
// q/k in [d*8+h] layout; q pre-scaled by QK_SCALE*log2(e); e = ex2(q.k).
// ---------------------------------------------------------------------------
__global__ __launch_bounds__(128) void attn_pass1(
    const float* __restrict__ qh, const float* __restrict__ kh,
    float* __restrict__ part)
{
    __shared__ float Ks[64 * 64];   // 16KB

    const int b    = blockIdx.z;
    const int sl   = blockIdx.y;
    const int tid  = threadIdx.x;
    const int warp = tid >> 5;
    const int lane = tid & 31;
    const size_t qi = (size_t)b * L_ + blockIdx.x * 128 + warp * 32 + lane;

    u64t q2[32];
    {
        const ulonglong2* qp = (const ulonglong2*)(qh + qi * 64);
#pragma unroll
        for (int j = 0; j < 16; j++) {
            ulonglong2 v = qp[j];
            q2[2 * j] = v.x; q2[2 * j + 1] = v.y;
        }
    }

    float sum[8];
#pragma unroll
    for (int h = 0; h < 8; h++) sum[h] = 0.0f;

    for (int c = 0; c < SLK / 64; c++) {
        __syncthreads();
        {
            const float4* src =
                (const float4*)(kh + ((size_t)b * L_ + sl * SLK + c * 64) * 64);
            float4* dst = (float4*)Ks;
#pragma unroll
            for (int j = 0; j < 8; j++)
                dst[tid + j * 128] = src[tid + j * 128];
        }
        __syncthreads();
#pragma unroll 2
        for (int mm = 0; mm < 64; mm++) {
            const ulonglong2* kp = (const ulonglong2*)(Ks + mm * 64);
            u64t acc[4];
            {
                ulonglong2 ka = kp[0], kc = kp[1];
                acc[0] = mul2(q2[0], ka.x);
                acc[1] = mul2(q2[1], ka.y);
                acc[2] = mul2(q2[2], kc.x);
                acc[3] = mul2(q2[3], kc.y);
            }
#pragma unroll
            for (int d = 1; d < 8; d++) {
                ulonglong2 ka = kp[2 * d], kc = kp[2 * d + 1];
                acc[0] = fma2(q2[d * 4 + 0], ka.x, acc[0]);
                acc[1] = fma2(q2[d * 4 + 1], ka.y, acc[1]);
                acc[2] = fma2(q2[d * 4 + 2], kc.x, acc[2]);
                acc[3] = fma2(q2[d * 4 + 3], kc.y, acc[3]);
            }
#pragma unroll
            for (int p = 0; p < 4; p++) {
                float lo, hi; unpack2(acc[p], lo, hi);
                sum[2 * p]     += ex2f(lo);
                sum[2 * p + 1] += ex2f(hi);
            }
        }
    }

    float4* op = (float4*)(part + qi * (NSL * 8) + sl * 8);
    op[0] = make_float4(sum[0], sum[1], sum[2], sum[3]);
    op[1] = make_float4(sum[4], sum[5], sum[6], sum[7]);
}

// ---------------------------------------------------------------------------
// Attention pass 2: per-slice unnormalized ctx partials + normalized
// attn_wts head-mean (slice-disjoint columns). inv computed from pass-1
// partials in the prologue; slice-0 blocks persist inv for the combiner.
// ---------------------------------------------------------------------------
__global__ __launch_bounds__(128) void attn_pass2(
    const float* __restrict__ qh, const float* __restrict__ kh,
    const float* __restrict__ vh, const float* __restrict__ part,
    float* __restrict__ ctxp, float* __restrict__ invout,
    float* __restrict__ attn_out)
{
    __shared__ float Ks[64 * 64];          // 16KB
    __shared__ float Vs[64 * 64];          // 16KB
    __shared__ float Wtile[4][32][17];     // 8.5KB

    const int b    = blockIdx.z;
    const int sl   = blockIdx.y;
    const int tid  = threadIdx.x;
    const int warp = tid >> 5;
    const int lane = tid & 31;
    const size_t qi = (size_t)b * L_ + blockIdx.x * 128 + warp * 32 + lane;

    u64t q2[32];
    {
        const ulonglong2* qp = (const ulonglong2*)(qh + qi * 64);
#pragma unroll
        for (int j = 0; j < 16; j++) {
            ulonglong2 v = qp[j];
            q2[2 * j] = v.x; q2[2 * j + 1] = v.y;
        }
    }

    // inv from per-slice partials
    float inv[8];
    {
        float s[8];
#pragma unroll
        for (int h = 0; h < 8; h++) s[h] = 0.0f;
        const float4* pp = (const float4*)(part + qi * (NSL * 8));
#pragma unroll
        for (int ss = 0; ss < NSL; ss++) {
            float4 a = pp[2 * ss], c = pp[2 * ss + 1];
            s[0] += a.x; s[1] += a.y; s[2] += a.z; s[3] += a.w;
            s[4] += c.x; s[5] += c.y; s[6] += c.z; s[7] += c.w;
        }
#pragma unroll
        for (int h = 0; h < 8; h++) inv[h] = 1.0f / s[h];
        if (sl == 0) {
            float4* op = (float4*)(invout + qi * 8);
            op[0] = make_float4(inv[0], inv[1], inv[2], inv[3]);
            op[1] = make_float4(inv[4], inv[5], inv[6], inv[7]);
        }
    }

    u64t ctx2[32];
#pragma unroll
    for (int j = 0; j < 32; j++) ctx2[j] = 0ull;

    for (int c = 0; c < SLK / 64; c++) {
        __syncthreads();
        {
            const float4* ksrc =
                (const float4*)(kh + ((size_t)b * L_ + sl * SLK + c * 64) * 64);
            const float4* vsrc =
                (const float4*)(vh + ((size_t)b * L_ + sl * SLK + c * 64) * 64);
            float4* kdst = (float4*)Ks;
            float4* vdst = (float4*)Vs;
#pragma unroll
            for (int j = 0; j < 8; j++) {
                kdst[tid + j * 128] = ksrc[tid + j * 128];
                vdst[tid + j * 128] = vsrc[tid + j * 128];
            }
        }
        __syncthreads();

        for (int m16 = 0; m16 < 64; m16 += 16) {
#pragma unroll 2
            for (int mm = 0; mm < 16; mm++) {
                const int m = m16 + mm;
                const ulonglong2* kp = (const ulonglong2*)(Ks + m * 64);
                u64t acc[4];
                {
                    ulonglong2 ka = kp[0], kc = kp[1];
                    acc[0] = mul2(q2[0], ka.x);
                    acc[1] = mul2(q2[1], ka.y);
                    acc[2] = mul2(q2[2], kc.x);
                    acc[3] = mul2(q2[3], kc.y);
                }
#pragma unroll
                for (int d = 1; d < 8; d++) {
                    ulonglong2 ka = kp[2 * d], kc = kp[2 * d + 1];
                    acc[0] = fma2(q2[d * 4 + 0], ka.x, acc[0]);
                    acc[1] = fma2(q2[d * 4 + 1], ka.y, acc[1]);
                    acc[2] = fma2(q2[d * 4 + 2], kc.x, acc[2]);
                    acc[3] = fma2(q2[d * 4 + 3], kc.y, acc[3]);
                }
                float e[8];
#pragma unroll
                for (int p = 0; p < 4; p++) {
                    float lo, hi; unpack2(acc[p], lo, hi);
                    e[2 * p]     = ex2f(lo);
                    e[2 * p + 1] = ex2f(hi);
                }
                float w = e[0] * inv[0];
#pragma unroll
                for (int h = 1; h < 8; h++) w = fmaf(e[h], inv[h], w);
                Wtile[warp][lane][mm] = w * 0.125f;

                u64t e2[4];
#pragma unroll
                for (int p = 0; p < 4; p++) e2[p] = pack2(e[2 * p], e[2 * p + 1]);

                const ulonglong2* vp = (const ulonglong2*)(Vs + m * 64);
#pragma unroll
                for (int d = 0; d < 8; d++) {
                    ulonglong2 va = vp[2 * d], vc = vp[2 * d + 1];
                    ctx2[d * 4 + 0] = fma2(e2[0], va.x, ctx2[d * 4 + 0]);
                    ctx2[d * 4 + 1] = fma2(e2[1], va.y, ctx2[d * 4 + 1]);
                    ctx2[d * 4 + 2] = fma2(e2[2], vc.x, ctx2[d * 4 + 2]);
                    ctx2[d * 4 + 3] = fma2(e2[3], vc.y, ctx2[d * 4 + 3]);
                }
            }
            // flush 32 queries x 16 keys (transposed -> coalesced 64B rows)
            __syncwarp();
            {
                const int m0 = sl * SLK + c * 64 + m16;
                float* arow = attn_out +
                    ((size_t)b * L_ + blockIdx.x * 128 + warp * 32) * L_ + m0;
                const int col = lane & 15;
#pragma unroll
                for (int rr = 0; rr < 16; rr++) {
                    int row = rr * 2 + (lane >> 4);
                    arow[(size_t)row * L_ + col] = Wtile[warp][row][col];
                }
            }
            __syncwarp();
        }
    }

    // store unnormalized ctx partial for this slice
    ulonglong2* cp = (ulonglong2*)(ctxp + (size_t)sl * ROWS * 64 + qi * 64);
#pragma unroll
    for (int d = 0; d < 8; d++) {
        ulonglong2 a, c;
        a.x = ctx2[d * 4 + 0]; a.y = ctx2[d * 4 + 1];
        c.x = ctx2[d * 4 + 2]; c.y = ctx2[d * 4 + 3];
        cp[2 * d] = a; cp[2 * d + 1] = c;
    }
}

// ---------------------------------------------------------------------------
// Combine ctx partials across slices and normalize by inv (per head).
// Output stays in [d*8+h] layout (Wo GEMM uses wperm).
// ---------------------------------------------------------------------------
__global__ __launch_bounds__(256) void ctx_combine(
    const float* __restrict__ ctxp, const float* __restrict__ invin,
    float* __restrict__ ctx)
{
    const int t  = blockIdx.x * 256 + threadIdx.x;   // 0 .. ROWS*16-1
    const int qi = t >> 4;
    const int j0 = (t & 15) * 4;

    float4 s = ((const float4*)(ctxp + (size_t)qi * 64 + j0))[0];
#pragma unroll
    for (int ss = 1; ss < NSL; ss++) {
        float4 a = ((const float4*)(ctxp + (size_t)ss * ROWS * 64 +
                                    (size_t)qi * 64 + j0))[0];
        s.x += a.x; s.y += a.y; s.z += a.z; s.w += a.w;
    }
    float4 iv = ((const float4*)(invin + (size_t)qi * 8 + (j0 & 4)))[0];
    s.x *= iv.x; s.y *= iv.y; s.z *= iv.z; s.w *= iv.w;
    ((float4*)(ctx + (size_t)qi * 64 + j0))[0] = s;
}

// ---------------------------------------------------------------------------
// Residual add + LayerNorm over E=64. One warp per row; lane covers 2 cols.
// ---------------------------------------------------------------------------
__global__ __launch_bounds__(256) void ln_add_kernel(
    const float* __restrict__ a, const float* __restrict__ bres,
    const float* __restrict__ g, const float* __restrict__ beta,
    float* __restrict__ out)
{
    const int warp = threadIdx.x >> 5;
    const int lane = threadIdx.x & 31;
    const int row  = blockIdx.x * 8 + warp;

    float2 av = ((const float2*)(a    + (size_t)row * 64))[lane];
    float2 bv = ((const float2*)(bres + (size_t)row * 64))[lane];
    float x0 = av.x + bv.x;
    float x1 = av.y + bv.y;

    float s  = x0 + x1;
    float sq = fmaf(x0, x0, x1 * x1);
#pragma unroll
    for (int o = 16; o > 0; o >>= 1) {
        s  += __shfl_xor_sync(0xffffffffu, s,  o);
        sq += __shfl_xor_sync(0xffffffffu, sq, o);
    }
    float mu   = s * (1.0f / 64.0f);
    float var  = sq * (1.0f / 64.0f) - mu * mu;
    float rstd = rsqrtf(var + 1e-5f);

    float2 gv = ((const float2*)g)[lane];
    float2 bb = ((const float2*)beta)[lane];
    float2 o2;
    o2.x = fmaf((x0 - mu) * rstd, gv.x, bb.x);
    o2.y = fmaf((x1 - mu) * rstd, gv.y, bb.y);
    ((float2*)(out + (size_t)row * 64))[lane] = o2;
}

// ---------------------------------------------------------------------------
extern "C" void kernel_launch(void* const* d_in, const int* in_sizes, int n_in,
                              void* d_out, int out_size)
{
    const float* q    = (const float*)d_in[0];
    const float* k    = (const float*)d_in[1];
    const float* prev = (const float*)d_in[2];
    const float* Wq   = (const float*)d_in[3];
    const float* bq   = (const float*)d_in[4];
    const float* Wk   = (const float*)d_in[5];
    const float* bk   = (const float*)d_in[6];
    const float* Wv   = (const float*)d_in[7];
    const float* bv   = (const float*)d_in[8];
    const float* Wo   = (const float*)d_in[9];
    const float* bo   = (const float*)d_in[10];
    const float* g1   = (const float*)d_in[11];
    const float* be1  = (const float*)d_in[12];
    const float* W1   = (const float*)d_in[13];
    const float* b1   = (const float*)d_in[14];
    const float* W2   = (const float*)d_in[15];
    const float* b2   = (const float*)d_in[16];
    const float* g2   = (const float*)d_in[17];
    const float* be2  = (const float*)d_in[18];

    float* outp = (float*)d_out;                    // [B, Lq, E]
    float* attn = outp + (size_t)ROWS * E_;         // [B, Lq, Lk]

    float *qh, *khp, *vhp, *ctx, *t0, *xbuf, *f1, *invb, *p1, *ctxp;
    cudaGetSymbolAddress((void**)&qh,  g_qh);
    cudaGetSymbolAddress((void**)&khp, g_kh);
    cudaGetSymbolAddress((void**)&vhp, g_vh);
    cudaGetSymbolAddress((void**)&ctx, g_ctx);
    cudaGetSymbolAddress((void**)&t0,  g_t0);
    cudaGetSymbolAddress((void**)&xbuf,g_x);
    cudaGetSymbolAddress((void**)&f1,  g_f1);
    cudaGetSymbolAddress((void**)&invb,g_inv);
    cudaGetSymbolAddress((void**)&p1,  g_p1);
    cudaGetSymbolAddress((void**)&ctxp,g_ctxp);

    const int GB = ROWS / 64;   // 512 blocks per gemm
    // projections into [d*8+h] layout; q pre-scaled by QK_SCALE*log2(e)
    gemm64<<<GB, 256>>>(q, Wq, bq, qh,  QK_SCALE * LOG2E_F, 0, 1, 0);
    gemm64<<<GB, 256>>>(k, Wk, bk, khp, 1.0f, 0, 1, 0);
    gemm64<<<GB, 256>>>(k, Wv, bv, vhp, 1.0f, 0, 1, 0);

    attn_pass1<<<dim3(L_ / 128, NSL, B_), 128>>>(qh, khp, p1);
    attn_pass2<<<dim3(L_ / 128, NSL, B_), 128>>>(qh, khp, vhp, p1, ctxp, invb, attn);
    ctx_combine<<<ROWS * 16 / 256, 256>>>(ctxp, invb, ctx);

    gemm64<<<GB, 256>>>(ctx, Wo, bo, t0, 1.0f, 0, 0, 1);
    ln_add_kernel<<<ROWS / 8, 256>>>(t0, prev, g1, be1, xbuf);

    gemm64<<<GB, 256>>>(xbuf, W1, b1, f1, 1.0f, 1, 0, 0);
    gemm64<<<GB, 256>>>(f1, W2, b2, t0, 1.0f, 0, 0, 0);
    ln_add_kernel<<<ROWS / 8, 256>>>(t0, xbuf, g2, be2, outp);
}